// round 16
// baseline (speedup 1.0000x reference)
#include <cuda_runtime.h>
#include <cstdint>

typedef unsigned long long u64;

#define DT_F      0.1f
#define NITERS    9               // int(1.0 // 0.1) == 9 in Python float semantics!
#define BATCH     64
#define NN        1024
#define NOBS      64
#define NACT      16
#define GROUPS    4               // groups of 32 CTAs
#define CPB       32              // CTAs per batch
#define ROWS_CTA  32              // rows per CTA per batch
#define BPG       (BATCH / GROUPS)   // 16 batches per group
#define PAIRS     (BPG / 2)          // 8 pairs (A in regs, B in smem)
#define NTHREADS  256

// y-exchange: 8-byte words = (tag<<32)|float_bits; y_t carries tag t+1, in buf[t&1].
__device__ u64 g_ybuf[2][BATCH][NN];

__global__ void ctrnn_init_kernel() {
    int i = blockIdx.x * blockDim.x + threadIdx.x;
    if (i < 2 * BATCH * NN) ((u64*)g_ybuf)[i] = 0ull;   // tag 0 = invalid
}

__device__ __forceinline__ u64 ldcg64(const u64* p) {
    u64 v;
    asm volatile("ld.global.cg.u64 %0, [%1];" : "=l"(v) : "l"(p));
    return v;
}
__device__ __forceinline__ void stcg64(u64* p, u64 v) {
    asm volatile("st.global.cg.u64 [%0], %1;" :: "l"(p), "l"(v) : "memory");
}

// packed f32x2 FMA: acc += a * b (elementwise on both 32-bit halves)
__device__ __forceinline__ void ffma2(u64& acc, u64 a, u64 b) {
    asm volatile("fma.rn.f32x2 %0, %1, %2, %0;" : "+l"(acc) : "l"(a), "l"(b));
}
__device__ __forceinline__ float unpack_sum(u64 acc) {
    float lo, hi;
    asm("mov.b64 {%0,%1}, %2;" : "=f"(lo), "=f"(hi) : "l"(acc));
    return lo + hi;
}

// gather 1024 tagged words (4/thread, strided 256), PARALLEL retry.
__device__ __forceinline__ void settle4(const u64* src, unsigned exp, float* y_s, int tid) {
    u64 r0 = ldcg64(src + tid);
    u64 r1 = ldcg64(src + tid + 256);
    u64 r2 = ldcg64(src + tid + 512);
    u64 r3 = ldcg64(src + tid + 768);
    for (;;) {
        const bool s0 = (unsigned)(r0 >> 32) != exp;
        const bool s1 = (unsigned)(r1 >> 32) != exp;
        const bool s2 = (unsigned)(r2 >> 32) != exp;
        const bool s3 = (unsigned)(r3 >> 32) != exp;
        if (!(s0 | s1 | s2 | s3)) break;
        __nanosleep(30);
        if (s0) r0 = ldcg64(src + tid);
        if (s1) r1 = ldcg64(src + tid + 256);
        if (s2) r2 = ldcg64(src + tid + 512);
        if (s3) r3 = ldcg64(src + tid + 768);
    }
    y_s[tid]       = __uint_as_float((unsigned)(r0 & 0xffffffffu));
    y_s[tid + 256] = __uint_as_float((unsigned)(r1 & 0xffffffffu));
    y_s[tid + 512] = __uint_as_float((unsigned)(r2 & 0xffffffffu));
    y_s[tid + 768] = __uint_as_float((unsigned)(r3 & 0xffffffffu));
}

__device__ __forceinline__ void mbar_init(uint32_t a, uint32_t cnt) {
    asm volatile("mbarrier.init.shared.b64 [%0], %1;" :: "r"(a), "r"(cnt) : "memory");
}
__device__ __forceinline__ void mbar_expect_tx(uint32_t a, uint32_t bytes) {
    asm volatile("mbarrier.arrive.expect_tx.shared.b64 _, [%0], %1;" :: "r"(a), "r"(bytes) : "memory");
}
__device__ __forceinline__ void mbar_wait(uint32_t a, uint32_t parity) {
    asm volatile(
        "{\n\t.reg .pred P;\n\t"
        "W_%=:\n\t"
        "mbarrier.try_wait.parity.shared.b64 P, [%0], %1;\n\t"
        "@P bra.uni D_%=;\n\t"
        "bra.uni W_%=;\n\t"
        "D_%=:\n\t}"
        :: "r"(a), "r"(parity) : "memory");
}
__device__ __forceinline__ void bulk_g2s(uint32_t dst, const void* src, uint32_t bytes, uint32_t mbar) {
    asm volatile(
        "cp.async.bulk.shared::cta.global.mbarrier::complete_tx::bytes [%0], [%1], %2, [%3];"
        :: "r"(dst), "l"(src), "r"(bytes), "r"(mbar) : "memory");
}
__device__ __forceinline__ void issue_chunks(uint32_t dst, const char* gsrc,
                                             uint32_t bytes, uint32_t mbar) {
    asm volatile("fence.proxy.async.shared::cta;" ::: "memory");
    mbar_expect_tx(mbar, bytes);
    for (uint32_t c = 0; c < bytes; c += 32768)
        bulk_g2s(dst + c, gsrc + c, 32768, mbar);
}

// SMEM layout (bytes):
//   S1 (batch B W, 32 rows)  : [0, 131072)
//   S0 (staging, 16 rows)    : [131072, 196608)
//   ysA[2][1024]             : [196608, 204800)
//   ysB[2][1024]             : [204800, 212992)
//   PA[6][32]                : [212992, 213760)
//   PB[6][32]                : [213760, 214528)
//   obs_s[64]                : [214528, 214784)
//   red_s[8]                 : [214784, 214816)
//   mbar0, mbar1             : [214816, 214832)
#define S1_OFF    0
#define S0_OFF    131072
#define YA_OFF    196608
#define YB_OFF    204800
#define PA_OFF    212992
#define PB_OFF    213760
#define OBS_OFF   214528
#define RED_OFF   214784
#define MB_OFF    214816
#define SMEM_BYTES 214832

// prologue for batch b: params -> P (stride 32), publish y0 (tag 1)
__device__ __forceinline__ void prologue(int b, int base, int tid,
    const float* __restrict__ obs, const float* __restrict__ v0,
    const float* __restrict__ tau, const float* __restrict__ gain,
    const float* __restrict__ bias, const float* __restrict__ mask,
    const float* __restrict__ E, float* P, float* obs_s)
{
    if (tid < NOBS) obs_s[tid] = obs[(size_t)b * NOBS + tid];
    __syncthreads();
    if (tid < ROWS_CTA) {
        const int n = base + tid;
        const size_t o = (size_t)b * NN + n;
        float vv = v0[o], gg = gain[o], bb = bias[o], mm = mask[o];
        P[0 * 32 + tid] = vv;
        P[1 * 32 + tid] = DT_F / tau[o];
        P[3 * 32 + tid] = gg;
        P[4 * 32 + tid] = bb;
        P[5 * 32 + tid] = mm;
        const float* Er = E + o * NOBS;
        float s = 0.f;
        #pragma unroll
        for (int q = 0; q < NOBS; q++) s += Er[q] * obs_s[q];
        P[2 * 32 + tid] = s;
        float y0 = tanhf(gg * (vv + bb)) * mm;
        stcg64(&g_ybuf[0][b][n], ((u64)1 << 32) | (u64)__float_as_uint(y0));
    }
    __syncthreads();   // obs_s free
}

__global__ __launch_bounds__(NTHREADS, 1)
void ctrnn_kernel(const float* __restrict__ obs,  const float* __restrict__ v0,
                  const float* __restrict__ tau,  const float* __restrict__ gain,
                  const float* __restrict__ bias, const float* __restrict__ W,
                  const float* __restrict__ mask, const float* __restrict__ E,
                  const float* __restrict__ D,    float* __restrict__ out)
{
    extern __shared__ char sm[];
    ulonglong2* S1v2 = (ulonglong2*)(sm + S1_OFF);   // batch B: 32 rows x 256 x 16B
    ulonglong2* S0v2 = (ulonglong2*)(sm + S0_OFF);   // staging 16 rows
    float*  ysA   = (float*)(sm + YA_OFF);           // [2][1024]
    float*  ysB   = (float*)(sm + YB_OFF);           // [2][1024]
    float*  PA    = (float*)(sm + PA_OFF);           // [6][32]
    float*  PB    = (float*)(sm + PB_OFF);
    float*  obs_s = (float*)(sm + OBS_OFF);
    float*  red_s = (float*)(sm + RED_OFF);

    const int tid  = threadIdx.x;
    const int warp = tid >> 5;
    const int lane = tid & 31;
    const int group = blockIdx.x >> 5;        // /32
    const int cig   = blockIdx.x & 31;
    const int base  = cig * ROWS_CTA;         // this CTA's 32 rows (per batch)

    const uint32_t mbar0 = (uint32_t)__cvta_generic_to_shared(sm + MB_OFF);
    const uint32_t mbar1 = mbar0 + 8;
    const uint32_t S0a   = (uint32_t)__cvta_generic_to_shared(S0v2);
    const uint32_t S1a   = (uint32_t)__cvta_generic_to_shared(S1v2);

    if (tid == 0) {
        mbar_init(mbar0, 1);
        mbar_init(mbar1, 1);
        asm volatile("fence.proxy.async.shared::cta;" ::: "memory");
    }
    __syncthreads();

    ulonglong2 Wreg[4][8];   // batch A: this warp's 4 rows x 8 16B-chunks
    int li0 = 0, li1 = 0;

    // ---------- pre-loop: assemble pair 0 ----------
    {
        const int bA0 = group * BPG;
        const char* gA = (const char*)(W + ((size_t)bA0 * NN + base) * NN);
        const char* gB = (const char*)(W + ((size_t)(bA0 + 1) * NN + base) * NN);
        if (tid == 0) issue_chunks(S0a, gA, 65536, mbar0);           // A0 part1
        prologue(bA0,     base, tid, obs, v0, tau, gain, bias, mask, E, PA, obs_s);
        prologue(bA0 + 1, base, tid, obs, v0, tau, gain, bias, mask, E, PB, obs_s);

        mbar_wait(mbar0, (uint32_t)(li0 & 1)); li0++;
        if (warp < 4) {
            #pragma unroll
            for (int r = 0; r < 4; r++)
                #pragma unroll
                for (int j = 0; j < 8; j++)
                    Wreg[r][j] = S0v2[(warp * 4 + r) * 256 + j * 32 + lane];
        }
        __syncthreads();
        if (tid == 0) {
            issue_chunks(S0a, gA + 65536, 65536, mbar0);             // A0 part2
            issue_chunks(S1a, gB, 131072, mbar1);                    // B0 full
        }
        mbar_wait(mbar0, (uint32_t)(li0 & 1)); li0++;
        if (warp >= 4) {
            #pragma unroll
            for (int r = 0; r < 4; r++)
                #pragma unroll
                for (int j = 0; j < 8; j++)
                    Wreg[r][j] = S0v2[((warp - 4) * 4 + r) * 256 + j * 32 + lane];
        }
        mbar_wait(mbar1, (uint32_t)(li1 & 1)); li1++;
        __syncthreads();
        if (tid == 0 && PAIRS > 1) {
            const char* gn = (const char*)(W + ((size_t)(bA0 + 2) * NN + base) * NN);
            issue_chunks(S0a, gn, 65536, mbar0);                     // A1 part1
        }
    }

    for (int p = 0; p < PAIRS; p++) {
        const int bA = group * BPG + 2 * p;
        const int bB = bA + 1;
        const bool has_next = (p + 1 < PAIRS);

        // ================== iterations: interleaved A/B ==================
        const ulonglong2* S1w = S1v2 + (size_t)(warp * 4) * 256;
        for (int t = 1; t <= NITERS; t++) {
            // ---- batch A: settle (published one B-phase ago -> ~ready) ----
            float* yA = ysA + ((t - 1) & 1) * NN;
            settle4(&g_ybuf[(t - 1) & 1][bA][0], (unsigned)t, yA, tid);
            __syncthreads();
            {
                const ulonglong2* Y2 = (const ulonglong2*)yA;
                u64 a0 = 0, a1 = 0, a2 = 0, a3 = 0;
                #pragma unroll
                for (int j = 0; j < 8; j++) {
                    const ulonglong2 y2 = Y2[j * 32 + lane];
                    ulonglong2 w;
                    w = Wreg[0][j]; ffma2(a0, w.x, y2.x); ffma2(a0, w.y, y2.y);
                    w = Wreg[1][j]; ffma2(a1, w.x, y2.x); ffma2(a1, w.y, y2.y);
                    w = Wreg[2][j]; ffma2(a2, w.x, y2.x); ffma2(a2, w.y, y2.y);
                    w = Wreg[3][j]; ffma2(a3, w.x, y2.x); ffma2(a3, w.y, y2.y);
                }
                float f0 = unpack_sum(a0), f1 = unpack_sum(a1);
                float f2 = unpack_sum(a2), f3 = unpack_sum(a3);
                #pragma unroll
                for (int off = 16; off > 0; off >>= 1) {
                    f0 += __shfl_xor_sync(0xffffffffu, f0, off);
                    f1 += __shfl_xor_sync(0xffffffffu, f1, off);
                    f2 += __shfl_xor_sync(0xffffffffu, f2, off);
                    f3 += __shfl_xor_sync(0xffffffffu, f3, off);
                }
                if (lane < 4) {
                    float dot = (lane == 0) ? f0 : (lane == 1) ? f1 : (lane == 2) ? f2 : f3;
                    int r = warp * 4 + lane;
                    float v  = PA[0 * 32 + r];
                    float nv = (v + PA[1 * 32 + r] * (dot + PA[2 * 32 + r] - v)) * PA[5 * 32 + r];
                    PA[0 * 32 + r] = nv;
                    float ov = (t < NITERS)
                        ? tanhf(PA[3 * 32 + r] * (nv + PA[4 * 32 + r])) * PA[5 * 32 + r]
                        : nv;
                    stcg64(&g_ybuf[t & 1][bA][base + r],
                           ((u64)(unsigned)(t + 1) << 32) | (u64)__float_as_uint(ov));
                }
            }

            // ---- batch B: settle (published one A-phase ago -> ~ready) ----
            float* yB = ysB + ((t - 1) & 1) * NN;
            settle4(&g_ybuf[(t - 1) & 1][bB][0], (unsigned)t, yB, tid);
            __syncthreads();
            {
                const ulonglong2* Y2 = (const ulonglong2*)yB;
                u64 a0 = 0, a1 = 0, a2 = 0, a3 = 0;
                #pragma unroll
                for (int j = 0; j < 8; j++) {
                    const ulonglong2 y2 = Y2[j * 32 + lane];
                    ulonglong2 w;
                    w = S1w[0 * 256 + j * 32 + lane]; ffma2(a0, w.x, y2.x); ffma2(a0, w.y, y2.y);
                    w = S1w[1 * 256 + j * 32 + lane]; ffma2(a1, w.x, y2.x); ffma2(a1, w.y, y2.y);
                    w = S1w[2 * 256 + j * 32 + lane]; ffma2(a2, w.x, y2.x); ffma2(a2, w.y, y2.y);
                    w = S1w[3 * 256 + j * 32 + lane]; ffma2(a3, w.x, y2.x); ffma2(a3, w.y, y2.y);
                }
                float f0 = unpack_sum(a0), f1 = unpack_sum(a1);
                float f2 = unpack_sum(a2), f3 = unpack_sum(a3);
                #pragma unroll
                for (int off = 16; off > 0; off >>= 1) {
                    f0 += __shfl_xor_sync(0xffffffffu, f0, off);
                    f1 += __shfl_xor_sync(0xffffffffu, f1, off);
                    f2 += __shfl_xor_sync(0xffffffffu, f2, off);
                    f3 += __shfl_xor_sync(0xffffffffu, f3, off);
                }
                if (lane < 4) {
                    float dot = (lane == 0) ? f0 : (lane == 1) ? f1 : (lane == 2) ? f2 : f3;
                    int r = warp * 4 + lane;
                    float v  = PB[0 * 32 + r];
                    float nv = (v + PB[1 * 32 + r] * (dot + PB[2 * 32 + r] - v)) * PB[5 * 32 + r];
                    PB[0 * 32 + r] = nv;
                    float ov = (t < NITERS)
                        ? tanhf(PB[3 * 32 + r] * (nv + PB[4 * 32 + r])) * PB[5 * 32 + r]
                        : nv;
                    stcg64(&g_ybuf[t & 1][bB][base + r],
                           ((u64)(unsigned)(t + 1) << 32) | (u64)__float_as_uint(ov));
                }
            }
        }
        __syncthreads();   // all local S1/ysA/ysB/P reads done

        // ================== boundary: W assembly || decode || prologue ==================
        // decode D row prefetch (independent global load, issue early)
        const int dbatch = (cig < 16) ? bA : bB;
        const int act    = cig & 15;
        const float4 dv = ((const float4*)(D + ((size_t)dbatch * NACT + act) * NN))[tid];

        if (has_next) {
            // A'(p+1) part1 was prefetched during iterations -> registers now
            mbar_wait(mbar0, (uint32_t)(li0 & 1)); li0++;
            if (warp < 4) {
                #pragma unroll
                for (int r = 0; r < 4; r++)
                    #pragma unroll
                    for (int j = 0; j < 8; j++)
                        Wreg[r][j] = S0v2[(warp * 4 + r) * 256 + j * 32 + lane];
            }
            __syncthreads();   // S0 free, S1 reads done
            if (tid == 0) {
                const char* gA = (const char*)(W + ((size_t)(bA + 2) * NN + base) * NN);
                const char* gB = (const char*)(W + ((size_t)(bB + 2) * NN + base) * NN);
                issue_chunks(S0a, gA + 65536, 65536, mbar0);   // A' part2
                issue_chunks(S1a, gB, 131072, mbar1);          // B' full
            }
        }

        // decode: settle final v of my batch (stage into ysA parity-0)
        settle4(&g_ybuf[NITERS & 1][dbatch][0], (unsigned)(NITERS + 1), ysA, tid);
        __syncthreads();
        {
            float pd = dv.x * ysA[4 * tid]     + dv.y * ysA[4 * tid + 1]
                     + dv.z * ysA[4 * tid + 2] + dv.w * ysA[4 * tid + 3];
            #pragma unroll
            for (int off = 16; off > 0; off >>= 1)
                pd += __shfl_xor_sync(0xffffffffu, pd, off);
            if (lane == 0) red_s[warp] = pd;
        }
        __syncthreads();
        if (tid == 0) {
            float s = 0.f;
            #pragma unroll
            for (int j = 0; j < 8; j++) s += red_s[j];
            out[dbatch * NACT + act] = s;
        }

        if (has_next) {
            // next pair prologue (overlaps A'part2 + B' TMA flight)
            prologue(bA + 2, base, tid, obs, v0, tau, gain, bias, mask, E, PA, obs_s);
            prologue(bB + 2, base, tid, obs, v0, tau, gain, bias, mask, E, PB, obs_s);

            mbar_wait(mbar0, (uint32_t)(li0 & 1)); li0++;      // A' part2 in S0
            if (warp >= 4) {
                #pragma unroll
                for (int r = 0; r < 4; r++)
                    #pragma unroll
                    for (int j = 0; j < 8; j++)
                        Wreg[r][j] = S0v2[((warp - 4) * 4 + r) * 256 + j * 32 + lane];
            }
            mbar_wait(mbar1, (uint32_t)(li1 & 1)); li1++;      // B' in S1
            __syncthreads();                                   // S0 free
            if (tid == 0 && p + 2 < PAIRS) {
                const char* gn = (const char*)(W + ((size_t)(bA + 4) * NN + base) * NN);
                issue_chunks(S0a, gn, 65536, mbar0);           // A'' part1, flies during iters
            }
        }
        __syncthreads();
    }
}

extern "C" void kernel_launch(void* const* d_in, const int* in_sizes, int n_in,
                              void* d_out, int out_size) {
    const float* obs  = (const float*)d_in[0];
    const float* v0   = (const float*)d_in[1];
    const float* tau  = (const float*)d_in[2];
    const float* gain = (const float*)d_in[3];
    const float* bias = (const float*)d_in[4];
    const float* W    = (const float*)d_in[5];
    const float* mask = (const float*)d_in[6];
    const float* E    = (const float*)d_in[7];
    const float* D    = (const float*)d_in[8];
    float* out = (float*)d_out;

    cudaFuncSetAttribute(ctrnn_kernel,
                         cudaFuncAttributeMaxDynamicSharedMemorySize, SMEM_BYTES);

    // reset exchange tags each launch (tag-freshness invariant, graph-replay safe)
    ctrnn_init_kernel<<<(2 * BATCH * NN + 255) / 256, 256>>>();

    // 128 CTAs = 4 groups x 32; ~210 KB smem each -> 1 CTA/SM, all co-resident
    ctrnn_kernel<<<GROUPS * CPB, NTHREADS, SMEM_BYTES>>>(
        obs, v0, tau, gain, bias, W, mask, E, D, out);
}

// round 17
// speedup vs baseline: 1.1658x; 1.1658x over previous
#include <cuda_runtime.h>
#include <cstdint>

typedef unsigned long long u64;

#define DT_F      0.1f
#define NITERS    9               // int(1.0 // 0.1) == 9 in Python float semantics!
#define BATCH     64
#define NN        1024
#define NOBS      64
#define NACT      16
#define GROUPS    8               // groups of 16 CTAs; one batch at a time per group
#define CPB       16              // CTAs per batch
#define ROWS_CTA  64              // rows per CTA (32 in regs + 32 in smem)
#define BPG       (BATCH / GROUPS)   // 8 batches per group
#define NTHREADS  256

// y-exchange: 8-byte words = (tag<<32)|float_bits; y_t carries tag t+1, in buf[t&1].
__device__ u64 g_ybuf[2][BATCH][NN];

__global__ void ctrnn_init_kernel() {
    int i = blockIdx.x * blockDim.x + threadIdx.x;
    if (i < 2 * BATCH * NN) ((u64*)g_ybuf)[i] = 0ull;   // tag 0 = invalid
}

__device__ __forceinline__ u64 ldcg64(const u64* p) {
    u64 v;
    asm volatile("ld.global.cg.u64 %0, [%1];" : "=l"(v) : "l"(p));
    return v;
}
__device__ __forceinline__ void stcg64(u64* p, u64 v) {
    asm volatile("st.global.cg.u64 [%0], %1;" :: "l"(p), "l"(v) : "memory");
}

// packed f32x2 FMA: acc += a * b (elementwise on both 32-bit halves)
__device__ __forceinline__ void ffma2(u64& acc, u64 a, u64 b) {
    asm volatile("fma.rn.f32x2 %0, %1, %2, %0;" : "+l"(acc) : "l"(a), "l"(b));
}
__device__ __forceinline__ float unpack_sum(u64 acc) {
    float lo, hi;
    asm("mov.b64 {%0,%1}, %2;" : "=f"(lo), "=f"(hi) : "l"(acc));
    return lo + hi;
}

// verify ONE pair of tagged words (parallel retry), commit to y_s
__device__ __forceinline__ void settle_pair(const u64* src, unsigned exp, float* y_s,
                                            int tid, int o1, int o2, u64& a, u64& c) {
    for (;;) {
        const bool s0 = (unsigned)(a >> 32) != exp;
        const bool s1 = (unsigned)(c >> 32) != exp;
        if (!(s0 | s1)) break;
        __nanosleep(16);
        if (s0) a = ldcg64(src + tid + o1);
        if (s1) c = ldcg64(src + tid + o2);
    }
    y_s[tid + o1] = __uint_as_float((unsigned)(a & 0xffffffffu));
    y_s[tid + o2] = __uint_as_float((unsigned)(c & 0xffffffffu));
}

// full 1024-word settle (used for the deferred decode gather; tags long settled)
__device__ __forceinline__ void settle4(const u64* src, unsigned exp, float* y_s, int tid) {
    u64 r0 = ldcg64(src + tid);
    u64 r1 = ldcg64(src + tid + 256);
    u64 r2 = ldcg64(src + tid + 512);
    u64 r3 = ldcg64(src + tid + 768);
    for (;;) {
        const bool s0 = (unsigned)(r0 >> 32) != exp;
        const bool s1 = (unsigned)(r1 >> 32) != exp;
        const bool s2 = (unsigned)(r2 >> 32) != exp;
        const bool s3 = (unsigned)(r3 >> 32) != exp;
        if (!(s0 | s1 | s2 | s3)) break;
        __nanosleep(16);
        if (s0) r0 = ldcg64(src + tid);
        if (s1) r1 = ldcg64(src + tid + 256);
        if (s2) r2 = ldcg64(src + tid + 512);
        if (s3) r3 = ldcg64(src + tid + 768);
    }
    y_s[tid]       = __uint_as_float((unsigned)(r0 & 0xffffffffu));
    y_s[tid + 256] = __uint_as_float((unsigned)(r1 & 0xffffffffu));
    y_s[tid + 512] = __uint_as_float((unsigned)(r2 & 0xffffffffu));
    y_s[tid + 768] = __uint_as_float((unsigned)(r3 & 0xffffffffu));
}

__device__ __forceinline__ void mbar_init(uint32_t a, uint32_t cnt) {
    asm volatile("mbarrier.init.shared.b64 [%0], %1;" :: "r"(a), "r"(cnt) : "memory");
}
__device__ __forceinline__ void mbar_expect_tx(uint32_t a, uint32_t bytes) {
    asm volatile("mbarrier.arrive.expect_tx.shared.b64 _, [%0], %1;" :: "r"(a), "r"(bytes) : "memory");
}
__device__ __forceinline__ void mbar_wait(uint32_t a, uint32_t parity) {
    asm volatile(
        "{\n\t.reg .pred P;\n\t"
        "W_%=:\n\t"
        "mbarrier.try_wait.parity.shared.b64 P, [%0], %1;\n\t"
        "@P bra.uni D_%=;\n\t"
        "bra.uni W_%=;\n\t"
        "D_%=:\n\t}"
        :: "r"(a), "r"(parity) : "memory");
}
__device__ __forceinline__ void bulk_g2s(uint32_t dst, const void* src, uint32_t bytes, uint32_t mbar) {
    asm volatile(
        "cp.async.bulk.shared::cta.global.mbarrier::complete_tx::bytes [%0], [%1], %2, [%3];"
        :: "r"(dst), "l"(src), "r"(bytes), "r"(mbar) : "memory");
}
__device__ __forceinline__ void issue_chunks(uint32_t dst, const char* gsrc,
                                             uint32_t bytes, uint32_t mbar) {
    asm volatile("fence.proxy.async.shared::cta;" ::: "memory");
    mbar_expect_tx(mbar, bytes);
    for (uint32_t c = 0; c < bytes; c += 32768)
        bulk_g2s(dst + c, gsrc + c, 32768, mbar);
}

// SMEM layout (bytes):
//   S1 (smem W half, 32 rows)   : [0, 131072)
//   S0 (staging, 16 rows)       : [131072, 196608)
//   y_s[2][1024]                : [196608, 204800)
//   P[2][6][64]                 : [204800, 207872)   (double-buffered params)
//   obs_s[64]                   : [207872, 208128)
//   red_s[8]                    : [208128, 208160)
//   mbar0, mbar1                : [208160, 208176)
#define S1_OFF    0
#define S0_OFF    131072
#define YS_OFF    196608
#define P_OFF     204800
#define OBS_OFF   207872
#define RED_OFF   208128
#define MB_OFF    208160
#define SMEM_BYTES 208176

__global__ __launch_bounds__(NTHREADS, 1)
void ctrnn_kernel(const float* __restrict__ obs,  const float* __restrict__ v0,
                  const float* __restrict__ tau,  const float* __restrict__ gain,
                  const float* __restrict__ bias, const float* __restrict__ W,
                  const float* __restrict__ mask, const float* __restrict__ E,
                  const float* __restrict__ D,    float* __restrict__ out)
{
    extern __shared__ char sm[];
    ulonglong2* S1v2 = (ulonglong2*)(sm + S1_OFF);   // 32 rows x 256 x 16B
    ulonglong2* S0v2 = (ulonglong2*)(sm + S0_OFF);   // 16 rows x 256 x 16B
    float*  y_s0  = (float*)(sm + YS_OFF);           // parity 0
    float*  y_s1  = y_s0 + NN;                       // parity 1
    float*  Pbuf  = (float*)(sm + P_OFF);            // [2][6][64]
    float*  obs_s = (float*)(sm + OBS_OFF);
    float*  red_s = (float*)(sm + RED_OFF);

    const int tid  = threadIdx.x;
    const int warp = tid >> 5;
    const int lane = tid & 31;
    const int group = blockIdx.x >> 4;        // /16
    const int cig   = blockIdx.x & 15;
    const int base  = cig * ROWS_CTA;         // first of this CTA's 64 rows

    const uint32_t mbar0 = (uint32_t)__cvta_generic_to_shared(sm + MB_OFF);
    const uint32_t mbar1 = mbar0 + 8;
    const uint32_t S0a   = (uint32_t)__cvta_generic_to_shared(S0v2);
    const uint32_t S1a   = (uint32_t)__cvta_generic_to_shared(S1v2);

    if (tid == 0) {
        mbar_init(mbar0, 1);
        mbar_init(mbar1, 1);
        asm volatile("fence.proxy.async.shared::cta;" ::: "memory");
    }
    __syncthreads();

    if (tid == 0) {
        const char* g = (const char*)(W + ((size_t)(group * BPG) * NN + base) * NN);
        issue_chunks(S0a, g, 65536, mbar0);              // part1 of batch 0
        issue_chunks(S1a, g + 131072, 131072, mbar1);    // smem half of batch 0
    }

    // ---- batch 0 prologue (params -> P[0], publish y0 tag 1) ----
    {
        const int b0 = group * BPG;
        if (tid < NOBS) obs_s[tid] = obs[(size_t)b0 * NOBS + tid];
        __syncthreads();
        if (tid < ROWS_CTA) {
            float* Pn = Pbuf;                            // parity 0
            const int n = base + tid;
            const size_t o = (size_t)b0 * NN + n;
            float vv = v0[o], gg = gain[o], bb = bias[o], mm = mask[o];
            Pn[0 * 64 + tid] = vv;
            Pn[1 * 64 + tid] = DT_F / tau[o];
            Pn[3 * 64 + tid] = gg;
            Pn[4 * 64 + tid] = bb;
            Pn[5 * 64 + tid] = mm;
            const float* Er = E + o * NOBS;
            float s = 0.f;
            #pragma unroll
            for (int q = 0; q < NOBS; q++) s += Er[q] * obs_s[q];
            Pn[2 * 64 + tid] = s;
            float y0 = tanhf(gg * (vv + bb)) * mm;
            stcg64(&g_ybuf[0][b0][n], ((u64)1 << 32) | (u64)__float_as_uint(y0));
        }
    }

    ulonglong2 Wreg[4][8];   // this warp's 4 register rows x 8 16B-chunks
    int li0 = 0, li1 = 0;

    for (int bi = 0; bi < BPG; bi++) {
        const int b = group * BPG + bi;
        const char* gW = (const char*)(W + ((size_t)b * NN + base) * NN);
        float* Pc = Pbuf + (bi & 1) * 384;               // current params

        // ---------- batch start: assemble W ----------
        mbar_wait(mbar0, (uint32_t)(li0 & 1)); li0++;    // part1 in S0
        if (warp < 4) {
            #pragma unroll
            for (int r = 0; r < 4; r++)
                #pragma unroll
                for (int j = 0; j < 8; j++)
                    Wreg[r][j] = S0v2[(warp * 4 + r) * 256 + j * 32 + lane];
        }
        __syncthreads();                                 // S0 free
        if (tid == 0)
            issue_chunks(S0a, gW + 65536, 65536, mbar0); // part2 (S1 already in flight)

        mbar_wait(mbar0, (uint32_t)(li0 & 1)); li0++;    // part2 in S0
        if (warp >= 4) {
            #pragma unroll
            for (int r = 0; r < 4; r++)
                #pragma unroll
                for (int j = 0; j < 8; j++)
                    Wreg[r][j] = S0v2[((warp - 4) * 4 + r) * 256 + j * 32 + lane];
        }
        mbar_wait(mbar1, (uint32_t)(li1 & 1)); li1++;    // smem half in S1
        __syncthreads();                                 // S0 free, S1 + P ready
        if (tid == 0 && bi + 1 < BPG) {
            const char* gn = (const char*)(W + ((size_t)(b + 1) * NN + base) * NN);
            issue_chunks(S0a, gn, 65536, mbar0);         // next part1, flies during iters
        }

        // ---------- iterations (split-settle pipelined) ----------
        const ulonglong2* S1w = S1v2 + (size_t)(warp * 4) * 256;
        for (int t = 1; t <= NITERS; t++) {
            float* ys = (t & 1) ? y_s1 : y_s0;
            const u64* src = &g_ybuf[(t - 1) & 1][b][0];
            const unsigned exp = (unsigned)t;
            // issue ALL loads up-front (MLP), verify in halves
            u64 r0 = ldcg64(src + tid);
            u64 r1 = ldcg64(src + tid + 256);
            u64 r2 = ldcg64(src + tid + 512);
            u64 r3 = ldcg64(src + tid + 768);

            settle_pair(src, exp, ys, tid, 0, 256, r0, r1);
            __syncthreads();                             // y[0:512] ready
            const ulonglong2* Y2 = (const ulonglong2*)ys;

            u64 ar0 = 0, ar1 = 0, ar2 = 0, ar3 = 0;
            u64 as0 = 0, as1 = 0, as2 = 0, as3 = 0;
            #pragma unroll
            for (int j = 0; j < 4; j++) {                // first half: y[0:512]
                const ulonglong2 y2 = Y2[j * 32 + lane];
                ulonglong2 w;
                w = Wreg[0][j];                   ffma2(ar0, w.x, y2.x); ffma2(ar0, w.y, y2.y);
                w = Wreg[1][j];                   ffma2(ar1, w.x, y2.x); ffma2(ar1, w.y, y2.y);
                w = Wreg[2][j];                   ffma2(ar2, w.x, y2.x); ffma2(ar2, w.y, y2.y);
                w = Wreg[3][j];                   ffma2(ar3, w.x, y2.x); ffma2(ar3, w.y, y2.y);
                w = S1w[0 * 256 + j * 32 + lane]; ffma2(as0, w.x, y2.x); ffma2(as0, w.y, y2.y);
                w = S1w[1 * 256 + j * 32 + lane]; ffma2(as1, w.x, y2.x); ffma2(as1, w.y, y2.y);
                w = S1w[2 * 256 + j * 32 + lane]; ffma2(as2, w.x, y2.x); ffma2(as2, w.y, y2.y);
                w = S1w[3 * 256 + j * 32 + lane]; ffma2(as3, w.x, y2.x); ffma2(as3, w.y, y2.y);
            }

            settle_pair(src, exp, ys, tid, 512, 768, r2, r3);
            __syncthreads();                             // y[512:1024] ready

            #pragma unroll
            for (int j = 4; j < 8; j++) {                // second half
                const ulonglong2 y2 = Y2[j * 32 + lane];
                ulonglong2 w;
                w = Wreg[0][j];                   ffma2(ar0, w.x, y2.x); ffma2(ar0, w.y, y2.y);
                w = Wreg[1][j];                   ffma2(ar1, w.x, y2.x); ffma2(ar1, w.y, y2.y);
                w = Wreg[2][j];                   ffma2(ar2, w.x, y2.x); ffma2(ar2, w.y, y2.y);
                w = Wreg[3][j];                   ffma2(ar3, w.x, y2.x); ffma2(ar3, w.y, y2.y);
                w = S1w[0 * 256 + j * 32 + lane]; ffma2(as0, w.x, y2.x); ffma2(as0, w.y, y2.y);
                w = S1w[1 * 256 + j * 32 + lane]; ffma2(as1, w.x, y2.x); ffma2(as1, w.y, y2.y);
                w = S1w[2 * 256 + j * 32 + lane]; ffma2(as2, w.x, y2.x); ffma2(as2, w.y, y2.y);
                w = S1w[3 * 256 + j * 32 + lane]; ffma2(as3, w.x, y2.x); ffma2(as3, w.y, y2.y);
            }

            float fr0 = unpack_sum(ar0), fr1 = unpack_sum(ar1);
            float fr2 = unpack_sum(ar2), fr3 = unpack_sum(ar3);
            float fs0 = unpack_sum(as0), fs1 = unpack_sum(as1);
            float fs2 = unpack_sum(as2), fs3 = unpack_sum(as3);
            #pragma unroll
            for (int off = 16; off > 0; off >>= 1) {
                fr0 += __shfl_xor_sync(0xffffffffu, fr0, off);
                fr1 += __shfl_xor_sync(0xffffffffu, fr1, off);
                fr2 += __shfl_xor_sync(0xffffffffu, fr2, off);
                fr3 += __shfl_xor_sync(0xffffffffu, fr3, off);
                fs0 += __shfl_xor_sync(0xffffffffu, fs0, off);
                fs1 += __shfl_xor_sync(0xffffffffu, fs1, off);
                fs2 += __shfl_xor_sync(0xffffffffu, fs2, off);
                fs3 += __shfl_xor_sync(0xffffffffu, fs3, off);
            }

            if (lane < 8) {
                float dot;
                int rloc;
                if (lane < 4) {
                    dot  = (lane == 0) ? fr0 : (lane == 1) ? fr1 : (lane == 2) ? fr2 : fr3;
                    rloc = warp * 4 + lane;
                } else {
                    dot  = (lane == 4) ? fs0 : (lane == 5) ? fs1 : (lane == 6) ? fs2 : fs3;
                    rloc = 32 + warp * 4 + (lane - 4);
                }
                float v  = Pc[0 * 64 + rloc];
                float nv = (v + Pc[1 * 64 + rloc] * (dot + Pc[2 * 64 + rloc] - v)) * Pc[5 * 64 + rloc];
                Pc[0 * 64 + rloc] = nv;
                float ov = (t < NITERS)
                    ? tanhf(Pc[3 * 64 + rloc] * (nv + Pc[4 * 64 + rloc])) * Pc[5 * 64 + rloc]
                    : nv;
                stcg64(&g_ybuf[t & 1][b][base + rloc],
                       ((u64)(unsigned)(t + 1) << 32) | (u64)__float_as_uint(ov));
            }
        }
        __syncthreads();   // all local S1/ys reads done; publishes issued

        // ---------- boundary: DEFERRED decode(b-1) || W assembly || prologue(b+1) ----------
        // S1 free (local reads done): prefetch next smem half immediately
        if (tid == 0 && bi + 1 < BPG) {
            const char* gn = (const char*)(W + ((size_t)(b + 1) * NN + base) * NN);
            issue_chunks(S1a, gn + 131072, 131072, mbar1);
        }
        // decode the PREVIOUS batch: its final tags settled long ago (no skew wait)
        if (bi > 0) {
            const int bd = b - 1;
            const float4 dv = ((const float4*)(D + ((size_t)bd * NACT + cig) * NN))[tid];
            settle4(&g_ybuf[NITERS & 1][bd][0], (unsigned)(NITERS + 1), y_s0, tid);
            __syncthreads();
            float p = dv.x * y_s0[4 * tid]     + dv.y * y_s0[4 * tid + 1]
                    + dv.z * y_s0[4 * tid + 2] + dv.w * y_s0[4 * tid + 3];
            #pragma unroll
            for (int off = 16; off > 0; off >>= 1)
                p += __shfl_xor_sync(0xffffffffu, p, off);
            if (lane == 0) red_s[warp] = p;
        }
        // next-batch prologue (independent global loads, same latency window)
        float vv = 0.f, gg = 0.f, bb = 0.f, mm = 0.f;
        if (bi + 1 < BPG) {
            if (tid < NOBS) obs_s[tid] = obs[(size_t)(b + 1) * NOBS + tid];
            if (tid < ROWS_CTA) {
                float* Pn = Pbuf + ((bi + 1) & 1) * 384;
                const size_t o = (size_t)(b + 1) * NN + (base + tid);
                vv = v0[o]; gg = gain[o]; bb = bias[o]; mm = mask[o];
                Pn[0 * 64 + tid] = vv;
                Pn[1 * 64 + tid] = DT_F / tau[o];
                Pn[3 * 64 + tid] = gg;
                Pn[4 * 64 + tid] = bb;
                Pn[5 * 64 + tid] = mm;
            }
        }
        __syncthreads();   // red_s + obs_s ready
        if (bi > 0 && tid == 0) {
            float s = 0.f;
            #pragma unroll
            for (int j = 0; j < 8; j++) s += red_s[j];
            out[(b - 1) * NACT + cig] = s;
        }
        if (bi + 1 < BPG && tid < ROWS_CTA) {
            float* Pn = Pbuf + ((bi + 1) & 1) * 384;
            const int n = base + tid;
            const float* Er = E + ((size_t)(b + 1) * NN + n) * NOBS;
            float s = 0.f;
            #pragma unroll
            for (int q = 0; q < NOBS; q++) s += Er[q] * obs_s[q];
            Pn[2 * 64 + tid] = s;
            float y0 = tanhf(gg * (vv + bb)) * mm;
            stcg64(&g_ybuf[0][b + 1][n], ((u64)1 << 32) | (u64)__float_as_uint(y0));
        }
        __syncthreads();   // Pn / y_s0 safe before next batch
    }

    // ---------- epilogue: decode the last batch of this group ----------
    {
        const int bd = group * BPG + (BPG - 1);
        const float4 dv = ((const float4*)(D + ((size_t)bd * NACT + cig) * NN))[tid];
        settle4(&g_ybuf[NITERS & 1][bd][0], (unsigned)(NITERS + 1), y_s0, tid);
        __syncthreads();
        float p = dv.x * y_s0[4 * tid]     + dv.y * y_s0[4 * tid + 1]
                + dv.z * y_s0[4 * tid + 2] + dv.w * y_s0[4 * tid + 3];
        #pragma unroll
        for (int off = 16; off > 0; off >>= 1)
            p += __shfl_xor_sync(0xffffffffu, p, off);
        if (lane == 0) red_s[warp] = p;
        __syncthreads();
        if (tid == 0) {
            float s = 0.f;
            #pragma unroll
            for (int j = 0; j < 8; j++) s += red_s[j];
            out[bd * NACT + cig] = s;
        }
    }
}

extern "C" void kernel_launch(void* const* d_in, const int* in_sizes, int n_in,
                              void* d_out, int out_size) {
    const float* obs  = (const float*)d_in[0];
    const float* v0   = (const float*)d_in[1];
    const float* tau  = (const float*)d_in[2];
    const float* gain = (const float*)d_in[3];
    const float* bias = (const float*)d_in[4];
    const float* W    = (const float*)d_in[5];
    const float* mask = (const float*)d_in[6];
    const float* E    = (const float*)d_in[7];
    const float* D    = (const float*)d_in[8];
    float* out = (float*)d_out;

    cudaFuncSetAttribute(ctrnn_kernel,
                         cudaFuncAttributeMaxDynamicSharedMemorySize, SMEM_BYTES);

    // reset exchange tags each launch (tag-freshness invariant, graph-replay safe)
    ctrnn_init_kernel<<<(2 * BATCH * NN + 255) / 256, 256>>>();

    // 128 CTAs = 8 groups x 16; ~203 KB smem each -> 1 CTA/SM, all co-resident
    ctrnn_kernel<<<GROUPS * CPB, NTHREADS, SMEM_BYTES>>>(
        obs, v0, tau, gain, bias, W, mask, E, D, out);
}